// round 4
// baseline (speedup 1.0000x reference)
#include <cuda_runtime.h>
#include <cuda_bf16.h>

#define IW 1920
#define IH 1080
#define BXT 32             // threads x
#define TYT 6              // threads y
#define NTH (BXT * TYT)    // 192
#define TPW 128            // tile pixel width  (32 thr * 4 px)
#define TPH 12             // tile pixel height (6 thr * 2 rows)
#define SMW 136            // 4 pad + 128 + 4 pad floats per row
#define SMH 18             // 12 + 2*3 halo
#define NF4 ((SMW / 4) * SMH)   // 612

__device__ __forceinline__ unsigned fold9(unsigned b) {
    // 24-bit circular buffer = bytes [b0, b1, b0, 0] via one PRMT.
    // Result bit i set <=> 9 consecutive set bits at rotation i; high bits self-zero.
    unsigned v = __byte_perm(b, 0, 0x4010);
    v &= v >> 1;   // runs >= 2
    v &= v >> 2;   // runs >= 4
    v &= v >> 4;   // runs >= 8
    v &= v >> 1;   // runs >= 9
    return v;
}

__global__ __launch_bounds__(NTH)
void fast_score_kernel(const float* __restrict__ img,
                       float* __restrict__ out) {
    __shared__ __align__(16) float sm[SMH * SMW];

    const int n = blockIdx.z;
    const float* im = img + (size_t)n * (IH * IW);
    float* om = out + (size_t)n * (IH * IW);

    const int bx = blockIdx.x * TPW;
    const int by = blockIdx.y * TPH;
    const int tid = threadIdx.y * BXT + threadIdx.x;

    const bool interior = (blockIdx.x > 0) & (blockIdx.x < gridDim.x - 1) &
                          (blockIdx.y > 0) & (blockIdx.y < gridDim.y - 1);

    if (interior) {
        // Rows by-3..by+14, cols bx-4..bx+131 all in-bounds, 16B aligned.
        const float4* g = (const float4*)(im + (size_t)(by - 3) * IW + (bx - 4));
        #pragma unroll
        for (int k = 0; k < 4; k++) {
            int i = tid + k * NTH;
            if (i < NF4) {
                int ly = i / 34;
                int kx = i - ly * 34;
                ((float4*)sm)[i] = g[ly * (IW / 4) + kx];
            }
        }
    } else {
        for (int i = tid; i < SMH * SMW; i += NTH) {
            int ly = i / SMW;
            int lx = i - ly * SMW;
            int gy = min(max(by + ly - 3, 0), IH - 1);
            int gx = min(max(bx + lx - 4, 0), IW - 1);
            sm[i] = __ldg(&im[(size_t)gy * IW + gx]);
        }
    }
    __syncthreads();

    const int tx = threadIdx.x;
    const int pr0 = threadIdx.y * 2;        // first pixel row (tile coords)
    const int scol = tx * 4;                // aligned window start (smem col)
    const float* smb = sm + (size_t)pr0 * SMW + scol;

    // Centers for both pixel rows (one LDS.128 each).
    float4 C0 = *(const float4*)(smb + 3 * SMW + 4);
    float4 C1 = *(const float4*)(smb + 4 * SMW + 4);
    float c0[4] = {C0.x, C0.y, C0.z, C0.w};
    float c1[4] = {C1.x, C1.y, C1.z, C1.w};

    unsigned dk0[4] = {0,0,0,0}, br0[4] = {0,0,0,0};
    unsigned dk1[4] = {0,0,0,0}, br1[4] = {0,0,0,0};
    float w[12];

    #define LOADROW(r) {                                                    \
        const float4* p = (const float4*)(smb + (r) * SMW);                 \
        float4 A = p[0], B = p[1], C = p[2];                                \
        w[0]=A.x; w[1]=A.y; w[2]=A.z;  w[3]=A.w;                            \
        w[4]=B.x; w[5]=B.y; w[6]=B.z;  w[7]=B.w;                            \
        w[8]=C.x; w[9]=C.y; w[10]=C.z; w[11]=C.w; }

    // Same op order as reference: d = circle - center; d>=20 / d<=-20.
    // Disjoint-bit += lets ptxas alternate IMAD/IADD3 across fma+alu pipes.
    #define CMP(i, cc, dkm, brm, dx, bit) {                                 \
        float d = w[(i) + 4 + (dx)] - cc[i];                                \
        if (d >=  20.0f) dkm[i] += (1u << (bit));                           \
        if (d <= -20.0f) brm[i] += (1u << (bit)); }

    #define R2(cc, dkm, brm, dxa, ba, dxb, bb)                              \
        _Pragma("unroll") for (int i = 0; i < 4; i++) {                     \
            CMP(i, cc, dkm, brm, dxa, ba) CMP(i, cc, dkm, brm, dxb, bb) }
    #define R3(cc, dkm, brm, dxa, ba, dxb, bb, dxc, bc)                     \
        _Pragma("unroll") for (int i = 0; i < 4; i++) {                     \
            CMP(i, cc, dkm, brm, dxa, ba) CMP(i, cc, dkm, brm, dxb, bb)     \
            CMP(i, cc, dkm, brm, dxc, bc) }

    // Per-dy offset tables:
    // dy=-3:(-1,13)(0,12)(1,11)  dy=-2:(-2,14)(2,10)  dy=-1:(-3,15)(3,9)
    // dy= 0:(-3,0)(3,8)          dy=+1:(-3,1)(3,7)    dy=+2:(-2,2)(2,6)
    // dy=+3:(-1,3)(0,4)(1,5)
    LOADROW(0);                                  // p0 dy=-3
    R3(c0, dk0, br0, -1,13, 0,12, 1,11);
    LOADROW(1);                                  // p0 dy=-2 | p1 dy=-3
    R2(c0, dk0, br0, -2,14, 2,10);
    R3(c1, dk1, br1, -1,13, 0,12, 1,11);
    LOADROW(2);                                  // p0 dy=-1 | p1 dy=-2
    R2(c0, dk0, br0, -3,15, 3, 9);
    R2(c1, dk1, br1, -2,14, 2,10);
    LOADROW(3);                                  // p0 dy= 0 | p1 dy=-1
    R2(c0, dk0, br0, -3, 0, 3, 8);
    R2(c1, dk1, br1, -3,15, 3, 9);
    LOADROW(4);                                  // p0 dy=+1 | p1 dy= 0
    R2(c0, dk0, br0, -3, 1, 3, 7);
    R2(c1, dk1, br1, -3, 0, 3, 8);
    LOADROW(5);                                  // p0 dy=+2 | p1 dy=+1
    R2(c0, dk0, br0, -2, 2, 2, 6);
    R2(c1, dk1, br1, -3, 1, 3, 7);
    LOADROW(6);                                  // p0 dy=+3 | p1 dy=+2
    R3(c0, dk0, br0, -1, 3, 0, 4, 1, 5);
    R2(c1, dk1, br1, -2, 2, 2, 6);
    LOADROW(7);                                  // p1 dy=+3
    R3(c1, dk1, br1, -1, 3, 0, 4, 1, 5);

    #undef LOADROW
    #undef CMP
    #undef R2
    #undef R3

    float4 r0, r1;
    r0.x = (fold9(dk0[0]) | fold9(br0[0])) ? 1.0f : 0.0f;
    r0.y = (fold9(dk0[1]) | fold9(br0[1])) ? 1.0f : 0.0f;
    r0.z = (fold9(dk0[2]) | fold9(br0[2])) ? 1.0f : 0.0f;
    r0.w = (fold9(dk0[3]) | fold9(br0[3])) ? 1.0f : 0.0f;
    r1.x = (fold9(dk1[0]) | fold9(br1[0])) ? 1.0f : 0.0f;
    r1.y = (fold9(dk1[1]) | fold9(br1[1])) ? 1.0f : 0.0f;
    r1.z = (fold9(dk1[2]) | fold9(br1[2])) ? 1.0f : 0.0f;
    r1.w = (fold9(dk1[3]) | fold9(br1[3])) ? 1.0f : 0.0f;

    const int y0 = by + pr0;
    float* o = om + (size_t)y0 * IW + bx + scol;
    *(float4*)o = r0;
    *(float4*)(o + IW) = r1;
}

extern "C" void kernel_launch(void* const* d_in, const int* in_sizes, int n_in,
                              void* d_out, int out_size) {
    const float* img = (const float*)d_in[0];
    float* out = (float*)d_out;
    const int N = in_sizes[0] / (IH * IW);

    dim3 block(BXT, TYT, 1);
    dim3 grid(IW / TPW, IH / TPH, N);   // 15 x 90 x N (exact)
    fast_score_kernel<<<grid, block>>>(img, out);
}

// round 5
// speedup vs baseline: 1.0581x; 1.0581x over previous
#include <cuda_runtime.h>
#include <cuda_bf16.h>

#define IW 1920
#define IH 1080
#define BXT 32            // threads x
#define BYT 8             // threads y
#define PXW 4             // horizontal pixels per thread
#define TPW (BXT * PXW)   // 128 pixel-wide tile
#define SMW 136           // floats per smem row: 4 pad + 128 + 4 pad
#define SMH 14            // 8 rows + 2*3 halo
#define NF4 ((SMW / 4) * SMH)  // 476
#define NTH (BXT * BYT)   // 256

__device__ __forceinline__ unsigned fold9(unsigned b) {
    // 24-bit circular buffer = bytes [b0, b1, b0, 0] via one PRMT.
    // Result bit i set <=> 9 consecutive set bits starting at rotation i.
    // Bits >= 16 of the result self-zero (byte3 == 0), so no final mask.
    unsigned v = __byte_perm(b, 0, 0x4010);
    v &= v >> 1;   // runs >= 2
    v &= v >> 2;   // runs >= 4
    v &= v >> 4;   // runs >= 8
    v &= v >> 1;   // runs >= 9
    return v;
}

__global__ __launch_bounds__(NTH)
void fast_score_kernel(const float* __restrict__ img,
                       float* __restrict__ out) {
    __shared__ __align__(16) float sm[SMH * SMW];

    const int n = blockIdx.z;
    const float* im = img + (size_t)n * (IH * IW);
    float* om = out + (size_t)n * (IH * IW);

    const int bx = blockIdx.x * TPW;
    const int by = blockIdx.y * BYT;
    const int tid = threadIdx.y * BXT + threadIdx.x;

    const bool interior = (blockIdx.x > 0) & (blockIdx.x < gridDim.x - 1) &
                          (blockIdx.y > 0) & (blockIdx.y < gridDim.y - 1);

    if (interior) {
        // Tile covers rows by-3..by+10, cols bx-4..bx+131, all in-bounds,
        // 16B-aligned (bx % 128 == 0). Pure LDG.128/STS.128 fill.
        const float4* g = (const float4*)(im + (size_t)(by - 3) * IW + (bx - 4));
        #pragma unroll
        for (int k = 0; k < 2; k++) {
            int i = tid + k * NTH;
            if (i < NF4) {
                int ly = i / 34;
                int kx = i - ly * 34;
                ((float4*)sm)[i] = g[ly * (IW / 4) + kx];
            }
        }
    } else {
        // Boundary blocks: scalar fill with replicate clamp.
        #pragma unroll
        for (int k = 0; k < 8; k++) {
            int e = tid + k * NTH;
            if (e < SMH * SMW) {
                int ly = e / SMW;
                int lx = e - ly * SMW;
                int gy = min(max(by + ly - 3, 0), IH - 1);
                int gx = min(max(bx + lx - 4, 0), IW - 1);
                sm[e] = __ldg(&im[(size_t)gy * IW + gx]);
            }
        }
    }
    __syncthreads();

    // Pixel i of this thread: x0+i, x0 = bx + tx*4. smem col of x0 is tx*4+4.
    // w[j] (after LOADROW) = value at column x0 + j - 4 of that row.
    const int basei = (threadIdx.y + 3) * SMW + threadIdx.x * 4 + 4;

    float w[12], c[4];
    unsigned dk[4] = {0u, 0u, 0u, 0u};
    unsigned br[4] = {0u, 0u, 0u, 0u};

    #define LOADROW(dy) {                                                   \
        const float4* p = (const float4*)(sm + basei + (dy) * SMW - 4);     \
        float4 A = p[0], B = p[1], C = p[2];                                \
        w[0]=A.x; w[1]=A.y; w[2]=A.z;  w[3]=A.w;                            \
        w[4]=B.x; w[5]=B.y; w[6]=B.z;  w[7]=B.w;                            \
        w[8]=C.x; w[9]=C.y; w[10]=C.z; w[11]=C.w; }

    // Same op order as reference: d = circle - center; d >= 20 / d <= -20.
    // Disjoint-bit '+=' lets ptxas use IMAD/IADD3 (fma+alu pipes) instead of
    // LOP3-only OR chains (alu pipe), balancing the two pipes.
    #define CMP(i, dx, bit) {                                               \
        float d = w[(i) + 4 + (dx)] - c[i];                                 \
        if (d >=  20.0f) dk[i] += (1u << (bit));                            \
        if (d <= -20.0f) br[i] += (1u << (bit)); }

    #define ROW2(dxa, ba, dxb, bb)                                          \
        _Pragma("unroll") for (int i = 0; i < 4; i++) {                     \
            CMP(i, dxa, ba) CMP(i, dxb, bb) }
    #define ROW3(dxa, ba, dxb, bb, dxc, bc)                                 \
        _Pragma("unroll") for (int i = 0; i < 4; i++) {                     \
            CMP(i, dxa, ba) CMP(i, dxb, bb) CMP(i, dxc, bc) }

    LOADROW(0);
    c[0] = w[4]; c[1] = w[5]; c[2] = w[6]; c[3] = w[7];
    ROW2(-3, 0,  3, 8);                     // (0,-3)->0, (0,3)->8
    LOADROW(-3); ROW3(-1, 13, 0, 12, 1, 11);
    LOADROW(-2); ROW2(-2, 14, 2, 10);
    LOADROW(-1); ROW2(-3, 15, 3,  9);
    LOADROW( 1); ROW2(-3,  1, 3,  7);
    LOADROW( 2); ROW2(-2,  2, 2,  6);
    LOADROW( 3); ROW3(-1,  3, 0,  4, 1, 5);

    #undef LOADROW
    #undef CMP
    #undef ROW2
    #undef ROW3

    float4 r;
    r.x = (fold9(dk[0]) | fold9(br[0])) ? 1.0f : 0.0f;
    r.y = (fold9(dk[1]) | fold9(br[1])) ? 1.0f : 0.0f;
    r.z = (fold9(dk[2]) | fold9(br[2])) ? 1.0f : 0.0f;
    r.w = (fold9(dk[3]) | fold9(br[3])) ? 1.0f : 0.0f;

    const int y = by + threadIdx.y;
    *(float4*)(om + (size_t)y * IW + bx + threadIdx.x * 4) = r;
}

extern "C" void kernel_launch(void* const* d_in, const int* in_sizes, int n_in,
                              void* d_out, int out_size) {
    const float* img = (const float*)d_in[0];
    float* out = (float*)d_out;
    const int N = in_sizes[0] / (IH * IW);

    dim3 block(BXT, BYT, 1);
    dim3 grid(IW / TPW, IH / BYT, N);   // 15 x 135 x N (exact)
    fast_score_kernel<<<grid, block>>>(img, out);
}

// round 6
// speedup vs baseline: 1.0906x; 1.0308x over previous
#include <cuda_runtime.h>
#include <cuda_bf16.h>

#define IW 1920
#define IH 1080
#define BXT 32            // threads x
#define BYT 8             // threads y
#define NTH (BXT * BYT)   // 256
#define NG 3              // row-groups per block (sequential)
#define TPW 128           // tile pixel width (32 thr * 4 px)
#define TPH (BYT * NG)    // 24 pixel rows per block
#define SMW 136           // floats per smem row: 4 pad + 128 + 4 pad
#define SMH (TPH + 6)     // 30 rows incl. halo
#define NF4 ((SMW / 4) * SMH)  // 34 * 30 = 1020

__device__ __forceinline__ unsigned fold9(unsigned b) {
    // 24-bit circular buffer = bytes [b0, b1, b0, 0] via one PRMT.
    // Result bit i set <=> 9 consecutive set bits starting at rotation i.
    // Bits >= 16 of the result self-zero (byte3 == 0), so no final mask.
    unsigned v = __byte_perm(b, 0, 0x4010);
    v &= v >> 1;   // runs >= 2
    v &= v >> 2;   // runs >= 4
    v &= v >> 4;   // runs >= 8
    v &= v >> 1;   // runs >= 9
    return v;
}

__global__ __launch_bounds__(NTH)
void fast_score_kernel(const float* __restrict__ img,
                       float* __restrict__ out) {
    __shared__ __align__(16) float sm[SMH * SMW];

    const int n = blockIdx.z;
    const float* im = img + (size_t)n * (IH * IW);
    float* om = out + (size_t)n * (IH * IW);

    const int bx = blockIdx.x * TPW;
    const int by = blockIdx.y * TPH;
    const int tid = threadIdx.y * BXT + threadIdx.x;

    const bool interior = (blockIdx.x > 0) & (blockIdx.x < gridDim.x - 1) &
                          (blockIdx.y > 0) & (blockIdx.y < gridDim.y - 1);

    if (interior) {
        // Tile covers rows by-3..by+26, cols bx-4..bx+131, all in-bounds,
        // 16B-aligned (bx % 128 == 0). Pure LDG.128/STS.128 fill.
        const float4* g = (const float4*)(im + (size_t)(by - 3) * IW + (bx - 4));
        #pragma unroll
        for (int k = 0; k < 4; k++) {
            int i = tid + k * NTH;
            if (i < NF4) {
                int ly = i / 34;
                int kx = i - ly * 34;
                ((float4*)sm)[i] = g[ly * (IW / 4) + kx];
            }
        }
    } else {
        // Boundary blocks: scalar fill with replicate clamp.
        for (int e = tid; e < SMH * SMW; e += NTH) {
            int ly = e / SMW;
            int lx = e - ly * SMW;
            int gy = min(max(by + ly - 3, 0), IH - 1);
            int gx = min(max(bx + lx - 4, 0), IW - 1);
            sm[e] = __ldg(&im[(size_t)gy * IW + gx]);
        }
    }
    __syncthreads();

    // Sequential row-groups: register state stays at one group's worth.
    #pragma unroll 1
    for (int g = 0; g < NG; g++) {
        const int pr = g * BYT + threadIdx.y;       // pixel row within tile
        const int basei = (pr + 3) * SMW + threadIdx.x * 4 + 4;

        float w[12], c[4];
        unsigned dk[4] = {0u, 0u, 0u, 0u};
        unsigned br[4] = {0u, 0u, 0u, 0u};

        #define LOADROW(dy) {                                                   \
            const float4* p = (const float4*)(sm + basei + (dy) * SMW - 4);     \
            float4 A = p[0], B = p[1], C = p[2];                                \
            w[0]=A.x; w[1]=A.y; w[2]=A.z;  w[3]=A.w;                            \
            w[4]=B.x; w[5]=B.y; w[6]=B.z;  w[7]=B.w;                            \
            w[8]=C.x; w[9]=C.y; w[10]=C.z; w[11]=C.w; }

        // Same op order as reference: d = circle - center; d>=20 / d<=-20.
        #define CMP(i, dx, bit) {                                               \
            float d = w[(i) + 4 + (dx)] - c[i];                                 \
            if (d >=  20.0f) dk[i] |= (1u << (bit));                            \
            if (d <= -20.0f) br[i] |= (1u << (bit)); }

        #define ROW2(dxa, ba, dxb, bb)                                          \
            _Pragma("unroll") for (int i = 0; i < 4; i++) {                     \
                CMP(i, dxa, ba) CMP(i, dxb, bb) }
        #define ROW3(dxa, ba, dxb, bb, dxc, bc)                                 \
            _Pragma("unroll") for (int i = 0; i < 4; i++) {                     \
                CMP(i, dxa, ba) CMP(i, dxb, bb) CMP(i, dxc, bc) }

        LOADROW(0);
        c[0] = w[4]; c[1] = w[5]; c[2] = w[6]; c[3] = w[7];
        ROW2(-3, 0,  3, 8);                     // (0,-3)->0, (0,3)->8
        LOADROW(-3); ROW3(-1, 13, 0, 12, 1, 11);
        LOADROW(-2); ROW2(-2, 14, 2, 10);
        LOADROW(-1); ROW2(-3, 15, 3,  9);
        LOADROW( 1); ROW2(-3,  1, 3,  7);
        LOADROW( 2); ROW2(-2,  2, 2,  6);
        LOADROW( 3); ROW3(-1,  3, 0,  4, 1, 5);

        #undef LOADROW
        #undef CMP
        #undef ROW2
        #undef ROW3

        float4 r;
        r.x = (fold9(dk[0]) | fold9(br[0])) ? 1.0f : 0.0f;
        r.y = (fold9(dk[1]) | fold9(br[1])) ? 1.0f : 0.0f;
        r.z = (fold9(dk[2]) | fold9(br[2])) ? 1.0f : 0.0f;
        r.w = (fold9(dk[3]) | fold9(br[3])) ? 1.0f : 0.0f;

        const int y = by + pr;
        *(float4*)(om + (size_t)y * IW + bx + threadIdx.x * 4) = r;
    }
}

extern "C" void kernel_launch(void* const* d_in, const int* in_sizes, int n_in,
                              void* d_out, int out_size) {
    const float* img = (const float*)d_in[0];
    float* out = (float*)d_out;
    const int N = in_sizes[0] / (IH * IW);

    dim3 block(BXT, BYT, 1);
    dim3 grid(IW / TPW, IH / TPH, N);   // 15 x 45 x N (exact)
    fast_score_kernel<<<grid, block>>>(img, out);
}